// round 1
// baseline (speedup 1.0000x reference)
#include <cuda_runtime.h>
#include <cstddef>

#define BLOC 16
#define NTHREADS (BLOC * 13)   // 208
#define NB 13
#define DD 16
#define BTOT 32768

struct Smem {
    float adj[BLOC * 676];        // [b_loc][i][n][m]
    float x[BLOC][NB][DD];        // per-b node features (also reused for temp)
    float iw[NB * DD];            // init_weight [m][d]
    float w0[4][DD * DD];         // mlp_w0 [l][d][e]
    float w1[4][DD * DD];
    float dw[4][DD * DD];         // dec_w [k][d][l]
    float fc1w[DD * DD];
    float fc2w[DD * DD];
    float b0[4][DD];
    float b1[4][DD];
    float db[4][DD];
    float fc1b[DD];
    float fc2b[DD];
    float eps[4];
};

#define LOAD16(dst, src) do {                                   \
    const float4* _p = (const float4*)(src);                    \
    float4 _a = _p[0], _b = _p[1], _c = _p[2], _d = _p[3];      \
    (dst)[0]=_a.x; (dst)[1]=_a.y; (dst)[2]=_a.z; (dst)[3]=_a.w; \
    (dst)[4]=_b.x; (dst)[5]=_b.y; (dst)[6]=_b.z; (dst)[7]=_b.w; \
    (dst)[8]=_c.x; (dst)[9]=_c.y; (dst)[10]=_c.z; (dst)[11]=_c.w;\
    (dst)[12]=_d.x;(dst)[13]=_d.y;(dst)[14]=_d.z;(dst)[15]=_d.w;\
} while (0)

#define STORE16(dst, src) do {                                  \
    float4* _p = (float4*)(dst);                                \
    _p[0] = make_float4((src)[0],(src)[1],(src)[2],(src)[3]);   \
    _p[1] = make_float4((src)[4],(src)[5],(src)[6],(src)[7]);   \
    _p[2] = make_float4((src)[8],(src)[9],(src)[10],(src)[11]); \
    _p[3] = make_float4((src)[12],(src)[13],(src)[14],(src)[15]);\
} while (0)

__device__ __forceinline__ float leaky(float v) {
    return v >= 0.f ? v : 0.01f * v;
}

// out[d] = bias[d] + sum_e v[e] * w[d*16+e]   (w, bias in shared; v, out in regs)
__device__ __forceinline__ void mat16(const float* __restrict__ w,
                                      const float* __restrict__ bias,
                                      const float* __restrict__ v,
                                      float* __restrict__ out)
{
#pragma unroll
    for (int d = 0; d < 16; d++) {
        const float4* row = (const float4*)(w + d * 16);
        float4 r0 = row[0], r1 = row[1], r2 = row[2], r3 = row[3];
        float acc = bias[d];
        acc = fmaf(v[0],  r0.x, acc); acc = fmaf(v[1],  r0.y, acc);
        acc = fmaf(v[2],  r0.z, acc); acc = fmaf(v[3],  r0.w, acc);
        acc = fmaf(v[4],  r1.x, acc); acc = fmaf(v[5],  r1.y, acc);
        acc = fmaf(v[6],  r1.z, acc); acc = fmaf(v[7],  r1.w, acc);
        acc = fmaf(v[8],  r2.x, acc); acc = fmaf(v[9],  r2.y, acc);
        acc = fmaf(v[10], r2.z, acc); acc = fmaf(v[11], r2.w, acc);
        acc = fmaf(v[12], r3.x, acc); acc = fmaf(v[13], r3.y, acc);
        acc = fmaf(v[14], r3.z, acc); acc = fmaf(v[15], r3.w, acc);
        out[d] = acc;
    }
}

__global__ void __launch_bounds__(NTHREADS, 3) vae_kernel(
    const float* __restrict__ adj,
    const float* __restrict__ init_weight,
    const float* __restrict__ eps_param,
    const float* __restrict__ mlp_w0, const float* __restrict__ mlp_b0,
    const float* __restrict__ mlp_w1, const float* __restrict__ mlp_b1,
    const float* __restrict__ big, const float* __restrict__ bib,
    const float* __restrict__ bim, const float* __restrict__ biv,
    const float* __restrict__ bog, const float* __restrict__ bob,
    const float* __restrict__ bom, const float* __restrict__ bov,
    const float* __restrict__ fc1w, const float* __restrict__ fc1b,
    const float* __restrict__ fc2w, const float* __restrict__ fc2b,
    const float* __restrict__ decw, const float* __restrict__ decb,
    float* __restrict__ out_recon,
    float* __restrict__ out_mu,
    float* __restrict__ out_logvar)
{
    extern __shared__ unsigned char smem_raw[];
    Smem* s = (Smem*)smem_raw;
    const int tid = threadIdx.x;

    // ---- cooperative staging: adj (vectorized, coalesced, read exactly once) ----
    {
        const float4* src = (const float4*)(adj + (size_t)blockIdx.x * (BLOC * 676));
        float4* dst = (float4*)s->adj;
#pragma unroll 1
        for (int i = tid; i < (BLOC * 676) / 4; i += NTHREADS) dst[i] = src[i];
    }
    // ---- weights to shared ----
#pragma unroll 1
    for (int i = tid; i < NB * DD; i += NTHREADS) s->iw[i] = init_weight[i];
#pragma unroll 1
    for (int i = tid; i < 4 * DD * DD; i += NTHREADS) {
        ((float*)s->w0)[i] = mlp_w0[i];
        ((float*)s->w1)[i] = mlp_w1[i];
        ((float*)s->dw)[i] = decw[i];
    }
#pragma unroll 1
    for (int i = tid; i < DD * DD; i += NTHREADS) {
        s->fc1w[i] = fc1w[i];
        s->fc2w[i] = fc2w[i];
    }
    if (tid < 4 * DD) {
        ((float*)s->b0)[tid] = mlp_b0[tid];
        ((float*)s->b1)[tid] = mlp_b1[tid];
        ((float*)s->db)[tid] = decb[tid];
    }
    if (tid < DD) {
        s->fc1b[tid] = fc1b[tid];
        s->fc2b[tid] = fc2b[tid];
    }
    if (tid < 4) s->eps[tid] = eps_param[tid];
    __syncthreads();

    const int b_loc = tid / 13;
    const int n = tid - b_loc * 13;
    const size_t b = (size_t)blockIdx.x * BLOC + b_loc;

    const float* ab = s->adj + b_loc * 676 + n * 13;   // adj rows for this node, 4 channels
    const float* xb = &s->x[b_loc][0][0];
    float* myx = &s->x[b_loc][n][0];

    // ---- init: x[n][d] = sum_m (sum_i adj[i][n][m]) * iw[m][d] ----
    float xr[16];
#pragma unroll
    for (int d = 0; d < 16; d++) xr[d] = 0.f;
#pragma unroll
    for (int m = 0; m < 13; m++) {
        float a = ab[m] + ab[169 + m] + ab[338 + m] + ab[507 + m];
        float w[16];
        LOAD16(w, s->iw + m * 16);
#pragma unroll
        for (int d = 0; d < 16; d++) xr[d] = fmaf(a, w[d], xr[d]);
    }
    STORE16(myx, xr);
    __syncthreads();

    // ---- 4 GIN layers (rolled to keep I$ footprint small) ----
#pragma unroll 1
    for (int l = 0; l < 4; l++) {
        const int bnidx = l * 13 + n;
        const float si = big[bnidx] * rsqrtf(biv[bnidx] + 1e-5f);
        const float ti = bib[bnidx] - bim[bnidx] * si;
        const float so = bog[bnidx] * rsqrtf(bov[bnidx] + 1e-5f);
        const float to = bob[bnidx] - bom[bnidx] * so;
        const float fe = 1.f + s->eps[l];

        float agg[16];
#pragma unroll
        for (int d = 0; d < 16; d++) agg[d] = fe * xr[d];
        // neighbor: channel i feeds feature group d in [4i,4i+4)
#pragma unroll
        for (int m = 0; m < 13; m++) {
            float a0 = ab[m], a1 = ab[169 + m], a2 = ab[338 + m], a3 = ab[507 + m];
            float xm[16];
            LOAD16(xm, xb + m * 16);
#pragma unroll
            for (int g = 0; g < 4; g++) {
                agg[g]      = fmaf(a0, xm[g],      agg[g]);
                agg[4 + g]  = fmaf(a1, xm[4 + g],  agg[4 + g]);
                agg[8 + g]  = fmaf(a2, xm[8 + g],  agg[8 + g]);
                agg[12 + g] = fmaf(a3, xm[12 + g], agg[12 + g]);
            }
        }
        float h1[16];
        mat16(s->w0[l], s->b0[l], agg, h1);
#pragma unroll
        for (int d = 0; d < 16; d++) h1[d] = leaky(fmaf(si, h1[d], ti));
        float h2[16];
        mat16(s->w1[l], s->b1[l], h1, h2);
#pragma unroll
        for (int d = 0; d < 16; d++) xr[d] = leaky(fmaf(so, h2[d], to));

        __syncthreads();                 // all reads of old x done
        STORE16(myx, xr);
        __syncthreads();                 // new x visible
    }

    // ---- heads: mu / logvar ----
    float mu[16], lv[16];
    mat16(s->fc1w, s->fc1b, xr, mu);
    mat16(s->fc2w, s->fc2b, xr, lv);
    {
        const size_t mbase = (b * 13 + (size_t)n) * 16;
        STORE16(out_mu + mbase, mu);
        STORE16(out_logvar + mbase, lv);
    }

    // ---- decoder: per k, temp = mu @ dec_w[k].T + dec_b[k]; recon = relu(temp temp^T) ----
#pragma unroll 1
    for (int k = 0; k < 4; k++) {
        float t[16];
        mat16(s->dw[k], s->db[k], mu, t);
        __syncthreads();                 // previous k's reads of s->x done
        STORE16(myx, t);
        __syncthreads();
        float* ro = out_recon + (((b * 4 + (size_t)k) * 13) + (size_t)n) * 13;
#pragma unroll
        for (int m = 0; m < 13; m++) {
            float tm[16];
            LOAD16(tm, xb + m * 16);
            float acc = t[0] * tm[0];
#pragma unroll
            for (int j = 1; j < 16; j++) acc = fmaf(t[j], tm[j], acc);
            ro[m] = fmaxf(acc, 0.f);
        }
    }
}

extern "C" void kernel_launch(void* const* d_in, const int* in_sizes, int n_in,
                              void* d_out, int out_size)
{
    const float* adj  = (const float*)d_in[0];
    const float* iw   = (const float*)d_in[1];
    const float* eps  = (const float*)d_in[2];
    const float* w0   = (const float*)d_in[3];
    const float* b0   = (const float*)d_in[4];
    const float* w1   = (const float*)d_in[5];
    const float* b1   = (const float*)d_in[6];
    const float* big  = (const float*)d_in[7];
    const float* bib  = (const float*)d_in[8];
    const float* bim  = (const float*)d_in[9];
    const float* biv  = (const float*)d_in[10];
    const float* bog  = (const float*)d_in[11];
    const float* bob  = (const float*)d_in[12];
    const float* bom  = (const float*)d_in[13];
    const float* bov  = (const float*)d_in[14];
    const float* f1w  = (const float*)d_in[15];
    const float* f1b  = (const float*)d_in[16];
    const float* f2w  = (const float*)d_in[17];
    const float* f2b  = (const float*)d_in[18];
    const float* dw   = (const float*)d_in[19];
    const float* db   = (const float*)d_in[20];

    float* out = (float*)d_out;
    float* recon = out;                                   // 32768*4*13*13
    float* mu    = out + (size_t)BTOT * 676;              // 32768*13*16
    float* lv    = mu  + (size_t)BTOT * 208;

    const int shmem = (int)sizeof(Smem);
    cudaFuncSetAttribute(vae_kernel, cudaFuncAttributeMaxDynamicSharedMemorySize, shmem);

    vae_kernel<<<BTOT / BLOC, NTHREADS, shmem>>>(
        adj, iw, eps, w0, b0, w1, b1,
        big, bib, bim, biv, bog, bob, bom, bov,
        f1w, f1b, f2w, f2b, dw, db,
        recon, mu, lv);
}

// round 2
// speedup vs baseline: 1.4689x; 1.4689x over previous
#include <cuda_runtime.h>
#include <cstddef>

#define BLOC 16
#define NTHREADS (BLOC * 13)   // 208
#define NB 13
#define DD 16
#define BTOT 32768

// ---------------- constant parameter block ----------------
struct CParams {
    float iw[NB][DD];          // init_weight [m][d]
    float w0[4][DD][DD];       // mlp_w0 [l][d][e]
    float w1[4][DD][DD];
    float dw[4][DD][DD];       // dec_w  [k][d][l]
    float fc1w[DD][DD];
    float fc2w[DD][DD];
    float b0[4][DD];
    float b1[4][DD];
    float db[4][DD];
    float fc1b[DD];
    float fc2b[DD];
    float si[4][NB];           // BN-in scale
    float ti[4][NB];           // BN-in offset
    float so[4][NB];           // BN-out scale
    float to[4][NB];           // BN-out offset
    float fe[4];               // 1 + eps
};

__constant__ CParams cP;
__device__ CParams gStage;     // staging (device-writable), memcpy'd into cP

// ---------------- pack kernel ----------------
__global__ void pack_kernel(
    const float* __restrict__ init_weight,
    const float* __restrict__ eps_param,
    const float* __restrict__ mlp_w0, const float* __restrict__ mlp_b0,
    const float* __restrict__ mlp_w1, const float* __restrict__ mlp_b1,
    const float* __restrict__ big, const float* __restrict__ bib,
    const float* __restrict__ bim, const float* __restrict__ biv,
    const float* __restrict__ bog, const float* __restrict__ bob,
    const float* __restrict__ bom, const float* __restrict__ bov,
    const float* __restrict__ fc1w, const float* __restrict__ fc1b,
    const float* __restrict__ fc2w, const float* __restrict__ fc2b,
    const float* __restrict__ decw, const float* __restrict__ decb)
{
    const int t = threadIdx.x;
    float* g = (float*)&gStage;
    CParams* s = &gStage;
    (void)g;
    for (int i = t; i < NB * DD; i += 256) ((float*)s->iw)[i] = init_weight[i];
    for (int i = t; i < 4 * DD * DD; i += 256) {
        ((float*)s->w0)[i] = mlp_w0[i];
        ((float*)s->w1)[i] = mlp_w1[i];
        ((float*)s->dw)[i] = decw[i];
    }
    for (int i = t; i < DD * DD; i += 256) {
        ((float*)s->fc1w)[i] = fc1w[i];
        ((float*)s->fc2w)[i] = fc2w[i];
    }
    if (t < 4 * DD) {
        ((float*)s->b0)[t] = mlp_b0[t];
        ((float*)s->b1)[t] = mlp_b1[t];
        ((float*)s->db)[t] = decb[t];
    }
    if (t < DD) {
        ((float*)s->fc1b)[t] = fc1b[t];
        ((float*)s->fc2b)[t] = fc2b[t];
    }
    if (t < 4 * NB) {
        float siv = big[t] * rsqrtf(biv[t] + 1e-5f);
        float sov = bog[t] * rsqrtf(bov[t] + 1e-5f);
        ((float*)s->si)[t] = siv;
        ((float*)s->ti)[t] = bib[t] - bim[t] * siv;
        ((float*)s->so)[t] = sov;
        ((float*)s->to)[t] = bob[t] - bom[t] * sov;
    }
    if (t < 4) s->fe[t] = 1.f + eps_param[t];
}

// ---------------- main kernel ----------------
struct Smem {
    float adj[BLOC * 676];        // [b_loc][i][n][m]
    float x[BLOC][NB][DD];        // per-b node features (reused for temp)
    float si[4 * NB];
    float ti[4 * NB];
    float so[4 * NB];
    float to[4 * NB];
    float fe[4];
};

#define LOAD16(dst, src) do {                                   \
    const float4* _p = (const float4*)(src);                    \
    float4 _a = _p[0], _b = _p[1], _c = _p[2], _d = _p[3];      \
    (dst)[0]=_a.x; (dst)[1]=_a.y; (dst)[2]=_a.z; (dst)[3]=_a.w; \
    (dst)[4]=_b.x; (dst)[5]=_b.y; (dst)[6]=_b.z; (dst)[7]=_b.w; \
    (dst)[8]=_c.x; (dst)[9]=_c.y; (dst)[10]=_c.z; (dst)[11]=_c.w;\
    (dst)[12]=_d.x;(dst)[13]=_d.y;(dst)[14]=_d.z;(dst)[15]=_d.w;\
} while (0)

#define STORE16(dst, src) do {                                  \
    float4* _p = (float4*)(dst);                                \
    _p[0] = make_float4((src)[0],(src)[1],(src)[2],(src)[3]);   \
    _p[1] = make_float4((src)[4],(src)[5],(src)[6],(src)[7]);   \
    _p[2] = make_float4((src)[8],(src)[9],(src)[10],(src)[11]); \
    _p[3] = make_float4((src)[12],(src)[13],(src)[14],(src)[15]);\
} while (0)

__device__ __forceinline__ float leaky(float v) {
    return v >= 0.f ? v : 0.01f * v;
}

// out[d] = bias[d] + sum_e v[e] * w[d][e]   (w, bias in __constant__; v, out in regs)
__device__ __forceinline__ void mat16c(const float (*__restrict__ w)[DD],
                                       const float* __restrict__ bias,
                                       const float* __restrict__ v,
                                       float* __restrict__ out)
{
#pragma unroll
    for (int d = 0; d < 16; d++) {
        float acc = bias[d];
#pragma unroll
        for (int e = 0; e < 16; e++) acc = fmaf(v[e], w[d][e], acc);
        out[d] = acc;
    }
}

__global__ void __launch_bounds__(NTHREADS, 4) vae_kernel(
    const float* __restrict__ adj,
    float* __restrict__ out_recon,
    float* __restrict__ out_mu,
    float* __restrict__ out_logvar)
{
    extern __shared__ unsigned char smem_raw[];
    Smem* s = (Smem*)smem_raw;
    const int tid = threadIdx.x;

    // ---- stage adj tile (vectorized, coalesced, read exactly once from HBM) ----
    {
        const float4* src = (const float4*)(adj + (size_t)blockIdx.x * (BLOC * 676));
        float4* dst = (float4*)s->adj;
#pragma unroll 1
        for (int i = tid; i < (BLOC * 676) / 4; i += NTHREADS) dst[i] = src[i];
    }
    // ---- stage BN affine params from global copy (avoids const-cache replay) ----
    if (tid < 4 * NB) {
        s->si[tid] = ((const float*)gStage.si)[tid];
        s->ti[tid] = ((const float*)gStage.ti)[tid];
        s->so[tid] = ((const float*)gStage.so)[tid];
        s->to[tid] = ((const float*)gStage.to)[tid];
    }
    if (tid < 4) s->fe[tid] = gStage.fe[tid];
    __syncthreads();

    const int b_loc = tid / 13;
    const int n = tid - b_loc * 13;
    const size_t b = (size_t)blockIdx.x * BLOC + b_loc;

    const float* ab = s->adj + b_loc * 676 + n * 13;
    const float* xb = &s->x[b_loc][0][0];
    float* myx = &s->x[b_loc][n][0];

    // ---- init: x[n][d] = sum_m (sum_i adj[i][n][m]) * iw[m][d] ----
    float xr[16];
#pragma unroll
    for (int d = 0; d < 16; d++) xr[d] = 0.f;
#pragma unroll
    for (int m = 0; m < 13; m++) {
        float a = ab[m] + ab[169 + m] + ab[338 + m] + ab[507 + m];
#pragma unroll
        for (int d = 0; d < 16; d++) xr[d] = fmaf(a, cP.iw[m][d], xr[d]);
    }
    STORE16(myx, xr);
    __syncthreads();

    // ---- 4 GIN layers ----
#pragma unroll 1
    for (int l = 0; l < 4; l++) {
        const int bnidx = l * 13 + n;
        const float si = s->si[bnidx];
        const float ti = s->ti[bnidx];
        const float so = s->so[bnidx];
        const float to = s->to[bnidx];
        const float fe = s->fe[l];

        float agg[16];
#pragma unroll
        for (int d = 0; d < 16; d++) agg[d] = fe * xr[d];
#pragma unroll
        for (int m = 0; m < 13; m++) {
            float a0 = ab[m], a1 = ab[169 + m], a2 = ab[338 + m], a3 = ab[507 + m];
            float xm[16];
            LOAD16(xm, xb + m * 16);
#pragma unroll
            for (int g = 0; g < 4; g++) {
                agg[g]      = fmaf(a0, xm[g],      agg[g]);
                agg[4 + g]  = fmaf(a1, xm[4 + g],  agg[4 + g]);
                agg[8 + g]  = fmaf(a2, xm[8 + g],  agg[8 + g]);
                agg[12 + g] = fmaf(a3, xm[12 + g], agg[12 + g]);
            }
        }
        float h1[16];
        mat16c(cP.w0[l], cP.b0[l], agg, h1);
#pragma unroll
        for (int d = 0; d < 16; d++) h1[d] = leaky(fmaf(si, h1[d], ti));
        float h2[16];
        mat16c(cP.w1[l], cP.b1[l], h1, h2);
#pragma unroll
        for (int d = 0; d < 16; d++) xr[d] = leaky(fmaf(so, h2[d], to));

        __syncthreads();
        STORE16(myx, xr);
        __syncthreads();
    }

    // ---- heads: mu / logvar ----
    float mu[16], lv[16];
    mat16c(cP.fc1w, cP.fc1b, xr, mu);
    mat16c(cP.fc2w, cP.fc2b, xr, lv);
    {
        const size_t mbase = (b * 13 + (size_t)n) * 16;
        STORE16(out_mu + mbase, mu);
        STORE16(out_logvar + mbase, lv);
    }

    // ---- decoder: per k, temp = mu @ dec_w[k].T + dec_b[k]; recon = relu(temp temp^T) ----
#pragma unroll 1
    for (int k = 0; k < 4; k++) {
        float t[16];
        mat16c(cP.dw[k], cP.db[k], mu, t);
        __syncthreads();
        STORE16(myx, t);
        __syncthreads();
        float* ro = out_recon + (((b * 4 + (size_t)k) * 13) + (size_t)n) * 13;
#pragma unroll
        for (int m = 0; m < 13; m++) {
            float tm[16];
            LOAD16(tm, xb + m * 16);
            float acc = t[0] * tm[0];
#pragma unroll
            for (int j = 1; j < 16; j++) acc = fmaf(t[j], tm[j], acc);
            ro[m] = fmaxf(acc, 0.f);
        }
    }
}

extern "C" void kernel_launch(void* const* d_in, const int* in_sizes, int n_in,
                              void* d_out, int out_size)
{
    const float* adj  = (const float*)d_in[0];
    const float* iw   = (const float*)d_in[1];
    const float* eps  = (const float*)d_in[2];
    const float* w0   = (const float*)d_in[3];
    const float* b0   = (const float*)d_in[4];
    const float* w1   = (const float*)d_in[5];
    const float* b1   = (const float*)d_in[6];
    const float* big  = (const float*)d_in[7];
    const float* bib  = (const float*)d_in[8];
    const float* bim  = (const float*)d_in[9];
    const float* biv  = (const float*)d_in[10];
    const float* bog  = (const float*)d_in[11];
    const float* bob  = (const float*)d_in[12];
    const float* bom  = (const float*)d_in[13];
    const float* bov  = (const float*)d_in[14];
    const float* f1w  = (const float*)d_in[15];
    const float* f1b  = (const float*)d_in[16];
    const float* f2w  = (const float*)d_in[17];
    const float* f2b  = (const float*)d_in[18];
    const float* dw   = (const float*)d_in[19];
    const float* db   = (const float*)d_in[20];

    float* out = (float*)d_out;
    float* recon = out;                                   // 32768*4*13*13
    float* mu    = out + (size_t)BTOT * 676;              // 32768*13*16
    float* lv    = mu  + (size_t)BTOT * 208;

    // 1) gather + precompute params into device staging
    pack_kernel<<<1, 256>>>(iw, eps, w0, b0, w1, b1,
                            big, bib, bim, biv, bog, bob, bom, bov,
                            f1w, f1b, f2w, f2b, dw, db);

    // 2) device-to-device copy into __constant__ (graph-capturable memcpy node)
    void* stage_ptr = nullptr;
    cudaGetSymbolAddress(&stage_ptr, gStage);
    cudaMemcpyToSymbolAsync(cP, stage_ptr, sizeof(CParams), 0,
                            cudaMemcpyDeviceToDevice, 0);

    // 3) main fused kernel
    const int shmem = (int)sizeof(Smem);
    cudaFuncSetAttribute(vae_kernel, cudaFuncAttributeMaxDynamicSharedMemorySize, shmem);
    vae_kernel<<<BTOT / BLOC, NTHREADS, shmem>>>(adj, recon, mu, lv);
}